// round 2
// baseline (speedup 1.0000x reference)
#include <cuda_runtime.h>
#include <cuda_bf16.h>

// Downsampler: (16,8,1024,1024) fp32, 4x4 Gaussian kernel, stride 4, VALID.
// Output (16,8,256,256) fp32. Non-overlapping windows -> pure streaming.
// R2: 4 outputs/thread -> 16 independent LDG.128 (MLP=16) + 1 STG.128.

#define N_  16
#define C_  8
#define H_  1024
#define W_  1024
#define F_  4
#define HO_ (H_ / F_)   // 256
#define WO_ (W_ / F_)   // 256
#define W4_ (W_ / 4)    // 256 float4 per input row
#define GPR_ (WO_ / 4)  // 64 output groups per row

__global__ __launch_bounds__(256) void Downsampler_24421184045082_kernel(
    const float* __restrict__ x,
    const float* __restrict__ kern,
    float* __restrict__ out,
    int ngroups)
{
    int g = blockIdx.x * blockDim.x + threadIdx.x;
    if (g >= ngroups) return;

    // g = ((nc * HO) + oh) * GPR + owg   (owg = group of 4 consecutive ow)
    int owg = g & (GPR_ - 1);          // 64 = 2^6
    int oh  = (g >> 6) & (HO_ - 1);    // 256 = 2^8
    int nc  = g >> 14;

    // Base of this thread's 4 adjacent 4x4 patches, as float4 rows.
    const float4* x4 = reinterpret_cast<const float4*>(x)
                     + (size_t)nc * (H_ * W4_)
                     + (size_t)(oh * F_) * W4_
                     + (owg << 2);

    // Hoist all 16 independent loads (4 rows x 4 patches) -> MLP=16.
    float4 d[4][4];
#pragma unroll
    for (int r = 0; r < 4; r++) {
#pragma unroll
        for (int p = 0; p < 4; p++) {
            d[r][p] = __ldg(x4 + r * W4_ + p);
        }
    }

    // Weights (uniform across warp; L1-cached after first warp).
    float k[4][4];
#pragma unroll
    for (int i = 0; i < 16; i++) ((float*)k)[i] = __ldg(kern + i);

    float acc[4] = {0.f, 0.f, 0.f, 0.f};
#pragma unroll
    for (int r = 0; r < 4; r++) {
#pragma unroll
        for (int p = 0; p < 4; p++) {
            acc[p] += k[r][0] * d[r][p].x + k[r][1] * d[r][p].y
                    + k[r][2] * d[r][p].z + k[r][3] * d[r][p].w;
        }
    }

    // One coalesced 128-bit store: 4 consecutive ow outputs.
    reinterpret_cast<float4*>(out)[g] =
        make_float4(acc[0], acc[1], acc[2], acc[3]);
}

extern "C" void kernel_launch(void* const* d_in, const int* in_sizes, int n_in,
                              void* d_out, int out_size)
{
    const float* x    = (const float*)d_in[0];   // (16,8,1024,1024) fp32
    const float* kern = (const float*)d_in[1];   // (4,4) fp32
    float* out = (float*)d_out;                  // (16,8,256,256) fp32

    int ngroups = N_ * C_ * HO_ * (WO_ / 4);     // 4,194,304
    int threads = 256;
    int blocks = (ngroups + threads - 1) / threads; // 16384
    Downsampler_24421184045082_kernel<<<blocks, threads>>>(x, kern, out, ngroups);
}